// round 4
// baseline (speedup 1.0000x reference)
#include <cuda_runtime.h>

#define BATCH 8
#define SEQ   2048
#define DIM   128
#define INV_TEMP 0.08838834764831844f   // 1/sqrt(128)

// ---------------------------------------------------------------------------
// zero the `out` region (d_out is poisoned; K3 accumulates with atomics)
// ---------------------------------------------------------------------------
__global__ void zero_out_kernel(float4* out) {
    int i = blockIdx.x * blockDim.x + threadIdx.x;
    out[i] = make_float4(0.f, 0.f, 0.f, 0.f);
}

// ---------------------------------------------------------------------------
// K1: S[b,i,j] = (1/sqrt(D)) * sum_d q[b,i,d] * v[b,j,d]
// 128x128 tile per block, K chunked by 32, 8x8 register micro-tile per thread
// ---------------------------------------------------------------------------
__global__ __launch_bounds__(256) void scores_kernel(
    const float* __restrict__ q, const float* __restrict__ v,
    float* __restrict__ attn)
{
    __shared__ float As[128][33];
    __shared__ float Bs[128][33];

    const int b  = blockIdx.z;
    const int i0 = blockIdx.y * 128;
    const int j0 = blockIdx.x * 128;
    const int tid = threadIdx.x;
    const int tx = tid & 15;
    const int ty = tid >> 4;

    const float* qb = q + (size_t)b * SEQ * DIM;
    const float* vb = v + (size_t)b * SEQ * DIM;

    float c[8][8];
#pragma unroll
    for (int m = 0; m < 8; m++)
#pragma unroll
        for (int n = 0; n < 8; n++) c[m][n] = 0.f;

    for (int k0 = 0; k0 < DIM; k0 += 32) {
#pragma unroll
        for (int t = 0; t < 16; t++) {
            int idx = tid + t * 256;          // 0..4095
            int r = idx >> 5, cc = idx & 31;
            As[r][cc] = qb[(size_t)(i0 + r) * DIM + k0 + cc];
            Bs[r][cc] = vb[(size_t)(j0 + r) * DIM + k0 + cc];
        }
        __syncthreads();
#pragma unroll
        for (int kk = 0; kk < 32; kk++) {
            float a[8], bb[8];
#pragma unroll
            for (int m = 0; m < 8; m++) a[m] = As[ty + m * 16][kk];
#pragma unroll
            for (int n = 0; n < 8; n++) bb[n] = Bs[tx + n * 16][kk];
#pragma unroll
            for (int m = 0; m < 8; m++)
#pragma unroll
                for (int n = 0; n < 8; n++) c[m][n] += a[m] * bb[n];
        }
        __syncthreads();
    }

    float* ab = attn + (size_t)b * SEQ * SEQ;
#pragma unroll
    for (int m = 0; m < 8; m++) {
        int row = i0 + ty + m * 16;
#pragma unroll
        for (int n = 0; n < 8; n++) {
            ab[(size_t)row * SEQ + j0 + tx + n * 16] = c[m][n] * INV_TEMP;
        }
    }
}

// ---------------------------------------------------------------------------
// K2: row-wise softmax in-place over attn. One block (256 thr) per row.
// Values held in registers (8 per thread) -> single gmem read + write.
// ---------------------------------------------------------------------------
__global__ __launch_bounds__(256) void softmax_kernel(float* __restrict__ attn)
{
    float* p = attn + (size_t)blockIdx.x * SEQ;
    const int tid = threadIdx.x;

    float x[8];
    float m = -1e30f;
#pragma unroll
    for (int t = 0; t < 8; t++) {
        x[t] = p[tid + t * 256];
        m = fmaxf(m, x[t]);
    }
#pragma unroll
    for (int o = 16; o; o >>= 1) m = fmaxf(m, __shfl_xor_sync(0xffffffffu, m, o));

    __shared__ float red[8];
    if ((tid & 31) == 0) red[tid >> 5] = m;
    __syncthreads();
    float bm = red[0];
#pragma unroll
    for (int w = 1; w < 8; w++) bm = fmaxf(bm, red[w]);
    __syncthreads();

    float s = 0.f;
#pragma unroll
    for (int t = 0; t < 8; t++) {
        x[t] = __expf(x[t] - bm);
        s += x[t];
    }
#pragma unroll
    for (int o = 16; o; o >>= 1) s += __shfl_xor_sync(0xffffffffu, s, o);
    if ((tid & 31) == 0) red[tid >> 5] = s;
    __syncthreads();
    float tot = 0.f;
#pragma unroll
    for (int w = 0; w < 8; w++) tot += red[w];

    const float inv = 1.0f / tot;
#pragma unroll
    for (int t = 0; t < 8; t++) p[tid + t * 256] = x[t] * inv;
}

// ---------------------------------------------------------------------------
// K3: out[b,j,d] = sum_i A[b,i,j] * v[b,i,d]   (A^T @ v)
// Block tile: 128 (j) x 128 (d); K(=i) split 8-way across blockIdx.y,
// partials accumulated with atomicAdd (out pre-zeroed).
// ---------------------------------------------------------------------------
#define KSPLIT 8
__global__ __launch_bounds__(256) void out_kernel(
    const float* __restrict__ attn, const float* __restrict__ v,
    float* __restrict__ out)
{
    __shared__ float As[32][128];
    __shared__ float Vs[32][128];

    const int b  = blockIdx.z;
    const int j0 = blockIdx.x * 128;
    const int tid = threadIdx.x;
    const int tx = tid & 15;
    const int ty = tid >> 4;

    const float* ab = attn + (size_t)b * SEQ * SEQ;
    const float* vb = v + (size_t)b * SEQ * DIM;

    float c[8][8];
#pragma unroll
    for (int m = 0; m < 8; m++)
#pragma unroll
        for (int n = 0; n < 8; n++) c[m][n] = 0.f;

    const int iBeg = blockIdx.y * (SEQ / KSPLIT);
    const int iEnd = iBeg + (SEQ / KSPLIT);
    for (int i0 = iBeg; i0 < iEnd; i0 += 32) {
#pragma unroll
        for (int t = 0; t < 16; t++) {
            int idx = tid + t * 256;          // 0..4095
            int r = idx >> 7, cc = idx & 127;
            As[r][cc] = ab[(size_t)(i0 + r) * SEQ + j0 + cc];
            Vs[r][cc] = vb[(size_t)(i0 + r) * DIM + cc];
        }
        __syncthreads();
#pragma unroll
        for (int kk = 0; kk < 32; kk++) {
            float a[8], w[8];
#pragma unroll
            for (int m = 0; m < 8; m++) a[m] = As[kk][ty + m * 16];
#pragma unroll
            for (int n = 0; n < 8; n++) w[n] = Vs[kk][tx + n * 16];
#pragma unroll
            for (int m = 0; m < 8; m++)
#pragma unroll
                for (int n = 0; n < 8; n++) c[m][n] += a[m] * w[n];
        }
        __syncthreads();
    }

    float* ob = out + (size_t)b * SEQ * DIM;
#pragma unroll
    for (int m = 0; m < 8; m++) {
        int row = j0 + ty + m * 16;
#pragma unroll
        for (int n = 0; n < 8; n++) {
            atomicAdd(&ob[(size_t)row * DIM + tx + n * 16], c[m][n]);
        }
    }
}

// ---------------------------------------------------------------------------
// launch: out region = d_out[0 : B*L*D), attn region = d_out[B*L*D : ...)
// inputs (metadata order): q, k (UNUSED by reference), v
// ---------------------------------------------------------------------------
extern "C" void kernel_launch(void* const* d_in, const int* in_sizes, int n_in,
                              void* d_out, int out_size)
{
    const float* q = (const float*)d_in[0];
    const float* v = (const float*)d_in[2];   // scores use v; k is unused

    float* out  = (float*)d_out;
    float* attn = out + (size_t)BATCH * SEQ * DIM;

    zero_out_kernel<<<(BATCH * SEQ * DIM) / 4 / 256, 256>>>((float4*)out);
    scores_kernel<<<dim3(SEQ / 128, SEQ / 128, BATCH), 256>>>(q, v, attn);
    softmax_kernel<<<BATCH * SEQ, 256>>>(attn);
    out_kernel<<<dim3(SEQ / 128, KSPLIT, BATCH), 256>>>(attn, v, out);
}

// round 7
// speedup vs baseline: 2.2978x; 2.2978x over previous
#include <cuda_runtime.h>
#include <cuda_bf16.h>
#include <cstdint>

#define BATCH 8
#define SEQ   2048
#define DIM   128
#define INV_TEMP 0.08838834764831844f   // 1/sqrt(128)

// per-row softmax stats scratch (device globals: allocation-free)
__device__ float g_rowM[BATCH * SEQ];
__device__ float g_rowInvS[BATCH * SEQ];

// ---------------------------------------------------------------------------
// warp-level bf16 MMA (sm_80+ HMMA; compiles for plain sm_103)
// D(m16n8,f32) += A(m16k16,bf16 row) * B(k16n8,bf16 col)
// ---------------------------------------------------------------------------
__device__ __forceinline__ void mma_bf16(float* d, const uint32_t* a,
                                         const uint32_t* b) {
    asm volatile(
        "mma.sync.aligned.m16n8k16.row.col.f32.bf16.bf16.f32 "
        "{%0,%1,%2,%3}, {%4,%5,%6,%7}, {%8,%9}, {%0,%1,%2,%3};\n"
        : "+f"(d[0]), "+f"(d[1]), "+f"(d[2]), "+f"(d[3])
        : "r"(a[0]), "r"(a[1]), "r"(a[2]), "r"(a[3]), "r"(b[0]), "r"(b[1]));
}

// split fp32 -> (hi, lo) bf16, store 4 consecutive elements (row-major, padded)
__device__ __forceinline__ void split_store4(__nv_bfloat16* hi, __nv_bfloat16* lo,
                                             int off, float4 x) {
    __nv_bfloat16 h0 = __float2bfloat16(x.x), h1 = __float2bfloat16(x.y);
    __nv_bfloat16 h2 = __float2bfloat16(x.z), h3 = __float2bfloat16(x.w);
    __nv_bfloat16 l0 = __float2bfloat16(x.x - __bfloat162float(h0));
    __nv_bfloat16 l1 = __float2bfloat16(x.y - __bfloat162float(h1));
    __nv_bfloat16 l2 = __float2bfloat16(x.z - __bfloat162float(h2));
    __nv_bfloat16 l3 = __float2bfloat16(x.w - __bfloat162float(h3));
    *(__nv_bfloat162*)(hi + off)     = __nv_bfloat162(h0, h1);
    *(__nv_bfloat162*)(hi + off + 2) = __nv_bfloat162(h2, h3);
    *(__nv_bfloat162*)(lo + off)     = __nv_bfloat162(l0, l1);
    *(__nv_bfloat162*)(lo + off + 2) = __nv_bfloat162(l2, l3);
}

// ---------------------------------------------------------------------------
// zero the `out` region (K3 accumulates with atomics)
// ---------------------------------------------------------------------------
__global__ void zero_out_kernel(float4* out) {
    int i = blockIdx.x * blockDim.x + threadIdx.x;
    out[i] = make_float4(0.f, 0.f, 0.f, 0.f);
}

// ---------------------------------------------------------------------------
// K1: raw scores S[b,i,j] = (q*INV_TEMP) . v  via HMMA, 3-term bf16 split
// 128x128 tile/block, 8 warps (2x4), warp tile 64x32, K chunked by 64
// smem: Ahi, Alo (q tile 128x64+pad), Bhi, Blo (v tile) -> 72 KB
// ---------------------------------------------------------------------------
#define LDT 72   // bf16 row stride (64 + 8 pad)

__global__ __launch_bounds__(256, 2)
void scores_mma_kernel(const float* __restrict__ q, const float* __restrict__ v,
                       float* __restrict__ attn) {
    extern __shared__ char smem[];
    __nv_bfloat16* Ahi = (__nv_bfloat16*)smem;
    __nv_bfloat16* Alo = Ahi + 128 * LDT;
    __nv_bfloat16* Bhi = Alo + 128 * LDT;
    __nv_bfloat16* Blo = Bhi + 128 * LDT;

    const int tid = threadIdx.x, wid = tid >> 5, lane = tid & 31;
    const int b = blockIdx.z, i0 = blockIdx.y * 128, j0 = blockIdx.x * 128;
    const int wm = wid >> 2, wn = wid & 3;    // 2 x 4 warp grid
    const int g = lane >> 2, tq = lane & 3;   // fragment lane coords

    float acc[4][4][4];
#pragma unroll
    for (int mt = 0; mt < 4; mt++)
#pragma unroll
        for (int nt = 0; nt < 4; nt++)
#pragma unroll
            for (int r = 0; r < 4; r++) acc[mt][nt][r] = 0.f;

    for (int kc = 0; kc < 2; kc++) {
        if (kc) __syncthreads();
        const float* qb = q + ((size_t)b * SEQ + i0) * DIM + kc * 64;
        const float* vb = v + ((size_t)b * SEQ + j0) * DIM + kc * 64;
#pragma unroll
        for (int t = 0; t < 8; t++) {
            int idx = tid + t * 256;
            int r = idx >> 4, c4 = (idx & 15) << 2;
            float4 xq = *(const float4*)(qb + (size_t)r * DIM + c4);
            xq.x *= INV_TEMP; xq.y *= INV_TEMP; xq.z *= INV_TEMP; xq.w *= INV_TEMP;
            split_store4(Ahi, Alo, r * LDT + c4, xq);
            float4 xv = *(const float4*)(vb + (size_t)r * DIM + c4);
            split_store4(Bhi, Blo, r * LDT + c4, xv);
        }
        __syncthreads();

#pragma unroll
        for (int ks = 0; ks < 4; ks++) {
            const int kb = ks * 16;
#pragma unroll
            for (int p = 0; p < 3; p++) {
                const __nv_bfloat16* At = (p == 2) ? Alo : Ahi;
                const __nv_bfloat16* Bt = (p == 1) ? Blo : Bhi;
                uint32_t a[4][4], bb[4][2];
#pragma unroll
                for (int mt = 0; mt < 4; mt++) {
                    int base = (wm * 64 + mt * 16 + g) * LDT + kb + tq * 2;
                    a[mt][0] = *(const uint32_t*)(At + base);
                    a[mt][1] = *(const uint32_t*)(At + base + 8 * LDT);
                    a[mt][2] = *(const uint32_t*)(At + base + 8);
                    a[mt][3] = *(const uint32_t*)(At + base + 8 * LDT + 8);
                }
#pragma unroll
                for (int nt = 0; nt < 4; nt++) {
                    int base = (wn * 32 + nt * 8 + g) * LDT + kb + tq * 2;
                    bb[nt][0] = *(const uint32_t*)(Bt + base);
                    bb[nt][1] = *(const uint32_t*)(Bt + base + 8);
                }
#pragma unroll
                for (int mt = 0; mt < 4; mt++)
#pragma unroll
                    for (int nt = 0; nt < 4; nt++)
                        mma_bf16(acc[mt][nt], a[mt], bb[nt]);
            }
        }
    }

    // epilogue: raw (already temperature-scaled) scores
#pragma unroll
    for (int mt = 0; mt < 4; mt++) {
        int row = i0 + wm * 64 + mt * 16 + g;
        float* r0 = attn + ((size_t)b * SEQ + row) * SEQ + j0;
        float* r1 = r0 + 8 * SEQ;
#pragma unroll
        for (int nt = 0; nt < 4; nt++) {
            int col = wn * 32 + nt * 8 + tq * 2;
            *(float2*)(r0 + col) = make_float2(acc[mt][nt][0], acc[mt][nt][1]);
            *(float2*)(r1 + col) = make_float2(acc[mt][nt][2], acc[mt][nt][3]);
        }
    }
}

// ---------------------------------------------------------------------------
// K2: per-row (over j) max and 1/sum(exp) of raw scores
// ---------------------------------------------------------------------------
__global__ __launch_bounds__(256) void rowstat_kernel(const float* __restrict__ attn) {
    const float* p = attn + (size_t)blockIdx.x * SEQ;
    const int tid = threadIdx.x;

    float x[8];
    float m = -1e30f;
#pragma unroll
    for (int t = 0; t < 8; t++) { x[t] = p[tid + t * 256]; m = fmaxf(m, x[t]); }
#pragma unroll
    for (int o = 16; o; o >>= 1) m = fmaxf(m, __shfl_xor_sync(0xffffffffu, m, o));

    __shared__ float red[8];
    if ((tid & 31) == 0) red[tid >> 5] = m;
    __syncthreads();
    float bm = red[0];
#pragma unroll
    for (int w = 1; w < 8; w++) bm = fmaxf(bm, red[w]);
    __syncthreads();

    float s = 0.f;
#pragma unroll
    for (int t = 0; t < 8; t++) s += __expf(x[t] - bm);
#pragma unroll
    for (int o = 16; o; o >>= 1) s += __shfl_xor_sync(0xffffffffu, s, o);
    if ((tid & 31) == 0) red[tid >> 5] = s;
    __syncthreads();
    if (tid == 0) {
        float tot = 0.f;
#pragma unroll
        for (int w = 0; w < 8; w++) tot += red[w];
        g_rowM[blockIdx.x] = bm;
        g_rowInvS[blockIdx.x] = 1.0f / tot;
    }
}

// ---------------------------------------------------------------------------
// K3: normalize attn in place AND out[b,j,d] += sum_i P[b,i,j]*v[b,i,d]
// P and v staged row-major [i][*]; transposed fragments gathered via LDS.U16.
// Warp tile 64(j) x 32(d); i chunked by 64; KSPLIT blocks accumulate w/ atomics
// ---------------------------------------------------------------------------
#define KSPLIT 2
#define LDP 136   // bf16 row stride for [64][128] slabs (128 + 8 pad)

__global__ __launch_bounds__(256, 2)
void out_mma_kernel(float* __restrict__ attn, const float* __restrict__ v,
                    float* __restrict__ out) {
    extern __shared__ char smem[];
    __nv_bfloat16* Phi = (__nv_bfloat16*)smem;
    __nv_bfloat16* Plo = Phi + 64 * LDP;
    __nv_bfloat16* Vhi = Plo + 64 * LDP;
    __nv_bfloat16* Vlo = Vhi + 64 * LDP;

    const int tid = threadIdx.x, wid = tid >> 5, lane = tid & 31;
    const int b = blockIdx.z, j0 = blockIdx.x * 128;
    const int wm = wid >> 2, wn = wid & 3;
    const int g = lane >> 2, tq = lane & 3;

    float acc[4][4][4];
#pragma unroll
    for (int mt = 0; mt < 4; mt++)
#pragma unroll
        for (int nt = 0; nt < 4; nt++)
#pragma unroll
            for (int r = 0; r < 4; r++) acc[mt][nt][r] = 0.f;

    const int iBase = blockIdx.y * (SEQ / KSPLIT);

    for (int chunk = 0; chunk < (SEQ / KSPLIT) / 64; chunk++) {
        const int i0 = iBase + chunk * 64;
        if (chunk) __syncthreads();

        // attn slab: exp-normalize, write back, stage hi/lo row-major [i][j]
        {
            float* abase = attn + ((size_t)b * SEQ + i0) * SEQ + j0;
#pragma unroll
            for (int t = 0; t < 8; t++) {
                int r = wid + t * 8;            // i-local; warp-uniform
                int c4 = lane << 2;             // j-local
                float m  = g_rowM[b * SEQ + i0 + r];
                float is = g_rowInvS[b * SEQ + i0 + r];
                float4 s4 = *(const float4*)(abase + (size_t)r * SEQ + c4);
                float4 p4;
                p4.x = __expf(s4.x - m) * is;
                p4.y = __expf(s4.y - m) * is;
                p4.z = __expf(s4.z - m) * is;
                p4.w = __expf(s4.w - m) * is;
                *(float4*)(abase + (size_t)r * SEQ + c4) = p4;
                split_store4(Phi, Plo, r * LDP + c4, p4);
            }
        }
        // v slab row-major [i][d]
        {
            const float* vbase = v + ((size_t)b * SEQ + i0) * DIM;
#pragma unroll
            for (int t = 0; t < 8; t++) {
                int r = wid + t * 8;
                int c4 = lane << 2;
                float4 x = *(const float4*)(vbase + (size_t)r * DIM + c4);
                split_store4(Vhi, Vlo, r * LDP + c4, x);
            }
        }
        __syncthreads();

#pragma unroll
        for (int ks = 0; ks < 4; ks++) {
            const int kb = ks * 16;             // i-local base
#pragma unroll
            for (int p = 0; p < 3; p++) {
                const __nv_bfloat16* At = (p == 2) ? Plo : Phi;
                const __nv_bfloat16* Bt = (p == 1) ? Vlo : Vhi;
                const int k0 = kb + tq * 2;
                uint32_t a[4][4], bb[4][2];
#pragma unroll
                for (int mt = 0; mt < 4; mt++) {
                    int row = wm * 64 + mt * 16 + g;      // j-local
                    const __nv_bfloat16* c0 = At + (size_t)k0 * LDP + row;
                    uint32_t x00 = *(const unsigned short*)(c0);
                    uint32_t x01 = *(const unsigned short*)(c0 + LDP);
                    uint32_t x80 = *(const unsigned short*)(c0 + 8 * LDP);
                    uint32_t x81 = *(const unsigned short*)(c0 + 9 * LDP);
                    uint32_t y00 = *(const unsigned short*)(c0 + 8);
                    uint32_t y01 = *(const unsigned short*)(c0 + LDP + 8);
                    uint32_t y80 = *(const unsigned short*)(c0 + 8 * LDP + 8);
                    uint32_t y81 = *(const unsigned short*)(c0 + 9 * LDP + 8);
                    a[mt][0] = x00 | (x01 << 16);
                    a[mt][1] = y00 | (y01 << 16);
                    a[mt][2] = x80 | (x81 << 16);
                    a[mt][3] = y80 | (y81 << 16);
                }
#pragma unroll
                for (int nt = 0; nt < 4; nt++) {
                    int col = wn * 32 + nt * 8 + g;       // d
                    const __nv_bfloat16* c0 = Bt + (size_t)k0 * LDP + col;
                    uint32_t x0 = *(const unsigned short*)(c0);
                    uint32_t x1 = *(const unsigned short*)(c0 + LDP);
                    uint32_t z0 = *(const unsigned short*)(c0 + 8 * LDP);
                    uint32_t z1 = *(const unsigned short*)(c0 + 9 * LDP);
                    bb[nt][0] = x0 | (x1 << 16);
                    bb[nt][1] = z0 | (z1 << 16);
                }
#pragma unroll
                for (int mt = 0; mt < 4; mt++)
#pragma unroll
                    for (int nt = 0; nt < 4; nt++)
                        mma_bf16(acc[mt][nt], a[mt], bb[nt]);
            }
        }
    }

    // epilogue: accumulate into out
#pragma unroll
    for (int mt = 0; mt < 4; mt++) {
        int row = j0 + wm * 64 + mt * 16 + g;
        float* r0 = out + ((size_t)b * SEQ + row) * DIM;
        float* r1 = r0 + 8 * DIM;
#pragma unroll
        for (int nt = 0; nt < 4; nt++) {
            int col = wn * 32 + nt * 8 + tq * 2;
            atomicAdd(r0 + col,     acc[mt][nt][0]);
            atomicAdd(r0 + col + 1, acc[mt][nt][1]);
            atomicAdd(r1 + col,     acc[mt][nt][2]);
            atomicAdd(r1 + col + 1, acc[mt][nt][3]);
        }
    }
}

// ---------------------------------------------------------------------------
#define SMEM_K1 (4 * 128 * LDT * 2)   // 73728
#define SMEM_K3 (4 * 64 * LDP * 2)    // 69632

extern "C" void kernel_launch(void* const* d_in, const int* in_sizes, int n_in,
                              void* d_out, int out_size) {
    const float* q = (const float*)d_in[0];
    const float* v = (const float*)d_in[2];   // reference uses v for scores; k unused

    float* out  = (float*)d_out;
    float* attn = out + (size_t)BATCH * SEQ * DIM;

    static int configured = 0;
    cudaFuncSetAttribute((const void*)scores_mma_kernel,
                         cudaFuncAttributeMaxDynamicSharedMemorySize, SMEM_K1);
    cudaFuncSetAttribute((const void*)out_mma_kernel,
                         cudaFuncAttributeMaxDynamicSharedMemorySize, SMEM_K3);
    (void)configured;

    zero_out_kernel<<<(BATCH * SEQ * DIM) / 4 / 256, 256>>>((float4*)out);
    scores_mma_kernel<<<dim3(SEQ / 128, SEQ / 128, BATCH), 256, SMEM_K1>>>(q, v, attn);
    rowstat_kernel<<<BATCH * SEQ, 256>>>(attn);
    out_mma_kernel<<<dim3(SEQ / 128, KSPLIT, BATCH), 256, SMEM_K3>>>(attn, v, out);
}

// round 10
// speedup vs baseline: 2.8739x; 1.2508x over previous
#include <cuda_runtime.h>
#include <cuda_bf16.h>
#include <cstdint>

#define BATCH 8
#define SEQ   2048
#define DIM   128
#define INV_TEMP 0.08838834764831844f   // 1/sqrt(128)

// ---------------------------------------------------------------------------
// warp-level bf16 MMA (sm_80+ HMMA)
// ---------------------------------------------------------------------------
__device__ __forceinline__ void mma_bf16(float* d, const uint32_t* a,
                                         const uint32_t* b) {
    asm volatile(
        "mma.sync.aligned.m16n8k16.row.col.f32.bf16.bf16.f32 "
        "{%0,%1,%2,%3}, {%4,%5,%6,%7}, {%8,%9}, {%0,%1,%2,%3};\n"
        : "+f"(d[0]), "+f"(d[1]), "+f"(d[2]), "+f"(d[3])
        : "r"(a[0]), "r"(a[1]), "r"(a[2]), "r"(a[3]), "r"(b[0]), "r"(b[1]));
}

__device__ __forceinline__ uint32_t cvta_smem(const void* p) {
    uint32_t a;
    asm("{ .reg .u64 t; cvta.to.shared.u64 t, %1; cvt.u32.u64 %0, t; }"
        : "=r"(a) : "l"(p));
    return a;
}
__device__ __forceinline__ void ldsm_x4(uint32_t* r, uint32_t addr) {
    asm volatile("ldmatrix.sync.aligned.m8n8.x4.shared.b16 {%0,%1,%2,%3}, [%4];"
                 : "=r"(r[0]), "=r"(r[1]), "=r"(r[2]), "=r"(r[3]) : "r"(addr));
}
__device__ __forceinline__ void ldsm_x4_t(uint32_t* r, uint32_t addr) {
    asm volatile("ldmatrix.sync.aligned.m8n8.x4.trans.shared.b16 {%0,%1,%2,%3}, [%4];"
                 : "=r"(r[0]), "=r"(r[1]), "=r"(r[2]), "=r"(r[3]) : "r"(addr));
}

// split fp32 -> (hi, lo) bf16, store 4 consecutive elements (row-major, padded)
__device__ __forceinline__ void split_store4(__nv_bfloat16* hi, __nv_bfloat16* lo,
                                             int off, float4 x) {
    __nv_bfloat16 h0 = __float2bfloat16(x.x), h1 = __float2bfloat16(x.y);
    __nv_bfloat16 h2 = __float2bfloat16(x.z), h3 = __float2bfloat16(x.w);
    __nv_bfloat16 l0 = __float2bfloat16(x.x - __bfloat162float(h0));
    __nv_bfloat16 l1 = __float2bfloat16(x.y - __bfloat162float(h1));
    __nv_bfloat16 l2 = __float2bfloat16(x.z - __bfloat162float(h2));
    __nv_bfloat16 l3 = __float2bfloat16(x.w - __bfloat162float(h3));
    *(__nv_bfloat162*)(hi + off)     = __nv_bfloat162(h0, h1);
    *(__nv_bfloat162*)(hi + off + 2) = __nv_bfloat162(h2, h3);
    *(__nv_bfloat162*)(lo + off)     = __nv_bfloat162(l0, l1);
    *(__nv_bfloat162*)(lo + off + 2) = __nv_bfloat162(l2, l3);
}

// ---------------------------------------------------------------------------
__global__ void zero_out_kernel(float4* out) {
    int i = blockIdx.x * blockDim.x + threadIdx.x;
    out[i] = make_float4(0.f, 0.f, 0.f, 0.f);
}

// ---------------------------------------------------------------------------
// K1: raw scores S[b,i,j] = (q*INV_TEMP) . v  via HMMA + ldmatrix
// 128x128 tile/block, 8 warps (2x4), warp tile 64x32, K chunked by 64
// ---------------------------------------------------------------------------
#define LDT 72   // bf16 row stride (64 + 8 pad)

__global__ __launch_bounds__(256, 2)
void scores_mma_kernel(const float* __restrict__ q, const float* __restrict__ v,
                       float* __restrict__ attn) {
    extern __shared__ char smem[];
    __nv_bfloat16* Ahi = (__nv_bfloat16*)smem;
    __nv_bfloat16* Alo = Ahi + 128 * LDT;
    __nv_bfloat16* Bhi = Alo + 128 * LDT;
    __nv_bfloat16* Blo = Bhi + 128 * LDT;
    const uint32_t sb = cvta_smem(smem);
    const uint32_t offT[3] = {0u, (uint32_t)(256 * 128 * LDT),          // A: hi,hi,lo
                              (uint32_t)(128 * LDT * 2)};               // (p index -> A off)
    // A offsets per p: p0 -> Ahi(0), p1 -> Ahi(0), p2 -> Alo
    // B offsets per p: p0 -> Bhi, p1 -> Blo, p2 -> Bhi
    const uint32_t offA[3] = {0u, 0u, (uint32_t)(128 * LDT * 2)};
    const uint32_t offB[3] = {(uint32_t)(2 * 128 * LDT * 2),
                              (uint32_t)(3 * 128 * LDT * 2),
                              (uint32_t)(2 * 128 * LDT * 2)};
    (void)offT;

    const int tid = threadIdx.x, wid = tid >> 5, lane = tid & 31;
    const int b = blockIdx.z, i0 = blockIdx.y * 128, j0 = blockIdx.x * 128;
    const int wm = wid >> 2, wn = wid & 3;    // 2 x 4 warp grid
    const int g = lane >> 2, tq = lane & 3;
    const int lrow = lane & 7, lt = lane >> 3;   // ldmatrix lane coords

    float acc[4][4][4];
#pragma unroll
    for (int mt = 0; mt < 4; mt++)
#pragma unroll
        for (int nt = 0; nt < 4; nt++)
#pragma unroll
            for (int r = 0; r < 4; r++) acc[mt][nt][r] = 0.f;

    for (int kc = 0; kc < 2; kc++) {
        if (kc) __syncthreads();
        const float* qb = q + ((size_t)b * SEQ + i0) * DIM + kc * 64;
        const float* vb = v + ((size_t)b * SEQ + j0) * DIM + kc * 64;
#pragma unroll
        for (int t = 0; t < 8; t++) {
            int idx = tid + t * 256;
            int r = idx >> 4, c4 = (idx & 15) << 2;
            float4 xq = *(const float4*)(qb + (size_t)r * DIM + c4);
            xq.x *= INV_TEMP; xq.y *= INV_TEMP; xq.z *= INV_TEMP; xq.w *= INV_TEMP;
            split_store4(Ahi, Alo, r * LDT + c4, xq);
            float4 xv = *(const float4*)(vb + (size_t)r * DIM + c4);
            split_store4(Bhi, Blo, r * LDT + c4, xv);
        }
        __syncthreads();

#pragma unroll
        for (int ks = 0; ks < 4; ks++) {
            const int kb = ks * 16;
#pragma unroll
            for (int p = 0; p < 3; p++) {
                uint32_t a[4][4], bb[4][2];
#pragma unroll
                for (int mt = 0; mt < 4; mt++) {
                    // A tile m16k16 at rows wm*64+mt*16, cols kb (non-trans)
                    int row = wm * 64 + mt * 16 + (lt & 1) * 8 + lrow;
                    int col = kb + (lt >> 1) * 8;
                    ldsm_x4(a[mt], sb + offA[p] + (uint32_t)(row * LDT + col) * 2);
                }
#pragma unroll
                for (int np = 0; np < 2; np++) {
                    // two n8 tiles packed in one x4: rows wn*32+np*16(+8), cols kb(+8)
                    int row = wn * 32 + np * 16 + (lt >> 1) * 8 + lrow;
                    int col = kb + (lt & 1) * 8;
                    uint32_t r4[4];
                    ldsm_x4(r4, sb + offB[p] + (uint32_t)(row * LDT + col) * 2);
                    bb[np * 2][0]     = r4[0];
                    bb[np * 2][1]     = r4[1];
                    bb[np * 2 + 1][0] = r4[2];
                    bb[np * 2 + 1][1] = r4[3];
                }
#pragma unroll
                for (int mt = 0; mt < 4; mt++)
#pragma unroll
                    for (int nt = 0; nt < 4; nt++)
                        mma_bf16(acc[mt][nt], a[mt], bb[nt]);
            }
        }
    }

#pragma unroll
    for (int mt = 0; mt < 4; mt++) {
        int row = i0 + wm * 64 + mt * 16 + g;
        float* r0 = attn + ((size_t)b * SEQ + row) * SEQ + j0;
        float* r1 = r0 + 8 * SEQ;
#pragma unroll
        for (int nt = 0; nt < 4; nt++) {
            int col = wn * 32 + nt * 8 + tq * 2;
            *(float2*)(r0 + col) = make_float2(acc[mt][nt][0], acc[mt][nt][1]);
            *(float2*)(r1 + col) = make_float2(acc[mt][nt][2], acc[mt][nt][3]);
        }
    }
}

// ---------------------------------------------------------------------------
// K2: fused row softmax in place (raw scores -> normalized probabilities)
// ---------------------------------------------------------------------------
__global__ __launch_bounds__(256) void softmax_kernel(float* __restrict__ attn) {
    float* p = attn + (size_t)blockIdx.x * SEQ;
    const int tid = threadIdx.x;

    float x[8];
    float m = -1e30f;
#pragma unroll
    for (int t = 0; t < 8; t++) { x[t] = p[tid + t * 256]; m = fmaxf(m, x[t]); }
#pragma unroll
    for (int o = 16; o; o >>= 1) m = fmaxf(m, __shfl_xor_sync(0xffffffffu, m, o));

    __shared__ float red[8];
    if ((tid & 31) == 0) red[tid >> 5] = m;
    __syncthreads();
    float bm = red[0];
#pragma unroll
    for (int w = 1; w < 8; w++) bm = fmaxf(bm, red[w]);
    __syncthreads();

    float s = 0.f;
#pragma unroll
    for (int t = 0; t < 8; t++) { x[t] = __expf(x[t] - bm); s += x[t]; }
#pragma unroll
    for (int o = 16; o; o >>= 1) s += __shfl_xor_sync(0xffffffffu, s, o);
    if ((tid & 31) == 0) red[tid >> 5] = s;
    __syncthreads();
    float tot = 0.f;
#pragma unroll
    for (int w = 0; w < 8; w++) tot += red[w];

    const float inv = 1.0f / tot;
#pragma unroll
    for (int t = 0; t < 8; t++) p[tid + t * 256] = x[t] * inv;
}

// ---------------------------------------------------------------------------
// K3: out[b,j,d] += sum_i P[b,i,j]*v[b,i,d]  (P already normalized)
// P, v staged row-major [i][*]; transposed fragments via ldmatrix.trans.
// Warp tile 64(j) x 32(d); i chunked by 64; KSPLIT blocks accumulate w/ atomics
// ---------------------------------------------------------------------------
#define KSPLIT 4
#define LDP 136   // bf16 row stride for [64][128] slabs (128 + 8 pad)

__global__ __launch_bounds__(256, 2)
void out_mma_kernel(const float* __restrict__ attn, const float* __restrict__ v,
                    float* __restrict__ out) {
    extern __shared__ char smem[];
    __nv_bfloat16* Phi = (__nv_bfloat16*)smem;
    __nv_bfloat16* Plo = Phi + 64 * LDP;
    __nv_bfloat16* Vhi = Plo + 64 * LDP;
    __nv_bfloat16* Vlo = Vhi + 64 * LDP;
    const uint32_t sb = cvta_smem(smem);
    const uint32_t offA[3] = {0u, 0u, (uint32_t)(64 * LDP * 2)};
    const uint32_t offB[3] = {(uint32_t)(2 * 64 * LDP * 2),
                              (uint32_t)(3 * 64 * LDP * 2),
                              (uint32_t)(2 * 64 * LDP * 2)};

    const int tid = threadIdx.x, wid = tid >> 5, lane = tid & 31;
    const int b = blockIdx.z, j0 = blockIdx.x * 128;
    const int wm = wid >> 2, wn = wid & 3;
    const int g = lane >> 2, tq = lane & 3;
    const int lrow = lane & 7, lt = lane >> 3;

    float acc[4][4][4];
#pragma unroll
    for (int mt = 0; mt < 4; mt++)
#pragma unroll
        for (int nt = 0; nt < 4; nt++)
#pragma unroll
            for (int r = 0; r < 4; r++) acc[mt][nt][r] = 0.f;

    const int iBase = blockIdx.y * (SEQ / KSPLIT);

    for (int chunk = 0; chunk < (SEQ / KSPLIT) / 64; chunk++) {
        const int i0 = iBase + chunk * 64;
        if (chunk) __syncthreads();

        // stage P slab [64][128] (normalized probabilities)
        {
            const float* abase = attn + ((size_t)b * SEQ + i0) * SEQ + j0;
#pragma unroll
            for (int t = 0; t < 8; t++) {
                int r = wid + t * 8;
                int c4 = lane << 2;
                float4 p4 = *(const float4*)(abase + (size_t)r * SEQ + c4);
                split_store4(Phi, Plo, r * LDP + c4, p4);
            }
        }
        // stage v slab [64][128]
        {
            const float* vbase = v + ((size_t)b * SEQ + i0) * DIM;
#pragma unroll
            for (int t = 0; t < 8; t++) {
                int r = wid + t * 8;
                int c4 = lane << 2;
                float4 x = *(const float4*)(vbase + (size_t)r * DIM + c4);
                split_store4(Vhi, Vlo, r * LDP + c4, x);
            }
        }
        __syncthreads();

#pragma unroll
        for (int ks = 0; ks < 4; ks++) {
            const int kb = ks * 16;             // i-local base
#pragma unroll
            for (int p = 0; p < 3; p++) {
                uint32_t a[4][4], bb[4][2];
#pragma unroll
                for (int mt = 0; mt < 4; mt++) {
                    // A = P^T tile m16k16 at j rows wm*64+mt*16, i cols kb (trans)
                    // lane: source row(i) = kb + (lt>>1)*8 + lrow, col(j) = R + (lt&1)*8
                    int R = wm * 64 + mt * 16;
                    int row = kb + (lt >> 1) * 8 + lrow;
                    int col = R + (lt & 1) * 8;
                    ldsm_x4_t(a[mt], sb + offA[p] + (uint32_t)(row * LDP + col) * 2);
                }
#pragma unroll
                for (int np = 0; np < 2; np++) {
                    // B = v^T: two n8 tiles packed; source row(i) = kb + (lt&1)*8 + lrow,
                    // col(d) = C + (lt>>1)*8
                    int C = wn * 32 + np * 16;
                    int row = kb + (lt & 1) * 8 + lrow;
                    int col = C + (lt >> 1) * 8;
                    uint32_t r4[4];
                    ldsm_x4_t(r4, sb + offB[p] + (uint32_t)(row * LDP + col) * 2);
                    bb[np * 2][0]     = r4[0];
                    bb[np * 2][1]     = r4[1];
                    bb[np * 2 + 1][0] = r4[2];
                    bb[np * 2 + 1][1] = r4[3];
                }
#pragma unroll
                for (int mt = 0; mt < 4; mt++)
#pragma unroll
                    for (int nt = 0; nt < 4; nt++)
                        mma_bf16(acc[mt][nt], a[mt], bb[nt]);
            }
        }
    }

    // epilogue: accumulate into out
#pragma unroll
    for (int mt = 0; mt < 4; mt++) {
        int row = j0 + wm * 64 + mt * 16 + g;
        float* r0 = out + ((size_t)b * SEQ + row) * DIM;
        float* r1 = r0 + 8 * DIM;
#pragma unroll
        for (int nt = 0; nt < 4; nt++) {
            int col = wn * 32 + nt * 8 + tq * 2;
            atomicAdd(r0 + col,     acc[mt][nt][0]);
            atomicAdd(r0 + col + 1, acc[mt][nt][1]);
            atomicAdd(r1 + col,     acc[mt][nt][2]);
            atomicAdd(r1 + col + 1, acc[mt][nt][3]);
        }
    }
}

// ---------------------------------------------------------------------------
#define SMEM_K1 (4 * 128 * LDT * 2)   // 73728
#define SMEM_K3 (4 * 64 * LDP * 2)    // 69632

extern "C" void kernel_launch(void* const* d_in, const int* in_sizes, int n_in,
                              void* d_out, int out_size) {
    const float* q = (const float*)d_in[0];
    const float* v = (const float*)d_in[2];   // reference uses v for scores; k unused

    float* out  = (float*)d_out;
    float* attn = out + (size_t)BATCH * SEQ * DIM;

    cudaFuncSetAttribute((const void*)scores_mma_kernel,
                         cudaFuncAttributeMaxDynamicSharedMemorySize, SMEM_K1);
    cudaFuncSetAttribute((const void*)out_mma_kernel,
                         cudaFuncAttributeMaxDynamicSharedMemorySize, SMEM_K3);

    zero_out_kernel<<<(BATCH * SEQ * DIM) / 4 / 256, 256>>>((float4*)out);
    scores_mma_kernel<<<dim3(SEQ / 128, SEQ / 128, BATCH), 256, SMEM_K1>>>(q, v, attn);
    softmax_kernel<<<BATCH * SEQ, 256>>>(attn);
    out_mma_kernel<<<dim3(SEQ / 128, KSPLIT, BATCH), 256, SMEM_K3>>>(attn, v, out);
}